// round 2
// baseline (speedup 1.0000x reference)
#include <cuda_runtime.h>

// Problem shape (fixed by the dataset)
#define NN 4096   // rows (num_states)
#define MM 4096   // cols
#define NSEG 32
#define RPS (NN / NSEG)   // 128 rows per segment

// Scratch (alloc-free: device globals)
__device__ float g_partials[NSEG * MM];  // 512 KB
__device__ float g_S[MM];                // logsumexp per column
__device__ float g_em1[NN];              // expm1(diag)

// ---------------------------------------------------------------------------
// Pass A: per-(segment, column) partial sums of exp(x).
// Grid: (MM/256, NSEG). Each thread owns one column within a 128-row segment.
// Coalesced: 256 consecutive columns per block -> 1024B contiguous per row.
// ---------------------------------------------------------------------------
__global__ __launch_bounds__(256) void k_colsum(const float* __restrict__ xx) {
    const int m   = blockIdx.x * 256 + threadIdx.x;
    const int seg = blockIdx.y;
    const float* p = xx + seg * RPS * MM + m;

    float a0 = 0.f, a1 = 0.f, a2 = 0.f, a3 = 0.f;
#pragma unroll 4
    for (int j = 0; j < RPS; j += 4) {
        float x0 = p[0 * MM];
        float x1 = p[1 * MM];
        float x2 = p[2 * MM];
        float x3 = p[3 * MM];
        p += 4 * MM;
        a0 += __expf(x0);
        a1 += __expf(x1);
        a2 += __expf(x2);
        a3 += __expf(x3);
    }
    g_partials[seg * MM + m] = (a0 + a1) + (a2 + a3);
}

// ---------------------------------------------------------------------------
// Pass B: reduce segment partials -> S[m] = log(colsum); also em1 = expm1(diag).
// Grid: MM/256 blocks (uses NN == MM so one launch covers both arrays).
// ---------------------------------------------------------------------------
__global__ __launch_bounds__(256) void k_finalize(const float* __restrict__ diag) {
    const int m = blockIdx.x * 256 + threadIdx.x;
    float c = 0.f;
#pragma unroll
    for (int s = 0; s < NSEG; s++) c += g_partials[s * MM + m];
    g_S[m]   = __logf(c);
    g_em1[m] = expm1f(diag[m]);
}

// ---------------------------------------------------------------------------
// Pass C: out[i,m] = S[m] + log(1 + em1[i] * exp(x[i,m] - S[m])).
// float4 vectorized; 4 rows per thread; streaming stores keep xx in L2.
// Grid: (MM/1024, NN/4), block 256.
// ---------------------------------------------------------------------------
__global__ __launch_bounds__(256) void k_out(const float* __restrict__ xx,
                                             float* __restrict__ out) {
    const int c4   = blockIdx.x * 256 + threadIdx.x;  // float4 column index
    const int row0 = blockIdx.y * 4;

    const float4 Sv = reinterpret_cast<const float4*>(g_S)[c4];

#pragma unroll
    for (int r = 0; r < 4; r++) {
        const int row = row0 + r;
        const float em1 = g_em1[row];
        const float4 x = reinterpret_cast<const float4*>(xx)[row * (MM / 4) + c4];
        float4 o;
        o.x = Sv.x + __logf(fmaf(em1, __expf(x.x - Sv.x), 1.0f));
        o.y = Sv.y + __logf(fmaf(em1, __expf(x.y - Sv.y), 1.0f));
        o.z = Sv.z + __logf(fmaf(em1, __expf(x.z - Sv.z), 1.0f));
        o.w = Sv.w + __logf(fmaf(em1, __expf(x.w - Sv.w), 1.0f));
        __stcs(reinterpret_cast<float4*>(out) + row * (MM / 4) + c4, o);
    }
}

extern "C" void kernel_launch(void* const* d_in, const int* in_sizes, int n_in,
                              void* d_out, int out_size) {
    const float* xx   = (const float*)d_in[0];   // (NN, MM) fp32 row-major
    const float* diag = (const float*)d_in[1];   // (NN,)   fp32
    float* out = (float*)d_out;                  // (NN, MM) fp32

    k_colsum<<<dim3(MM / 256, NSEG), 256>>>(xx);
    k_finalize<<<MM / 256, 256>>>(diag);
    k_out<<<dim3(MM / 1024, NN / 4), 256>>>(xx, out);
}